// round 3
// baseline (speedup 1.0000x reference)
#include <cuda_runtime.h>
#include <cuda_bf16.h>
#include <stdint.h>

// Problem constants (fixed shapes)
#define B_ROWS 2048
#define RSZ    10
#define DIM    1024
#define NTGT   (B_ROWS * (RSZ - 1))   // 18432 targets
#define INV_TEMP 20.0f
#define ALPHA_C  1.0f
#define BETA_C   0.5f

// ---------------- device scratch ----------------
__device__ __nv_bfloat16 g_an[(size_t)B_ROWS * DIM];   // normalized anchors (bf16)
__device__ __nv_bfloat16 g_tn[(size_t)NTGT * DIM];     // normalized targets (bf16)
__device__ float g_diag[B_ROWS];
__device__ float g_kl[B_ROWS];
__device__ float g_Z[B_ROWS];

__device__ __forceinline__ float warpReduceSum(float v) {
    v += __shfl_xor_sync(0xffffffffu, v, 16);
    v += __shfl_xor_sync(0xffffffffu, v, 8);
    v += __shfl_xor_sync(0xffffffffu, v, 4);
    v += __shfl_xor_sync(0xffffffffu, v, 2);
    v += __shfl_xor_sync(0xffffffffu, v, 1);
    return v;
}

__device__ __forceinline__ uint2 pack_bf16x4(float4 f) {
    __nv_bfloat162 lo = __floats2bfloat162_rn(f.x, f.y);
    __nv_bfloat162 hi = __floats2bfloat162_rn(f.z, f.w);
    uint2 u;
    u.x = *reinterpret_cast<unsigned int*>(&lo);
    u.y = *reinterpret_cast<unsigned int*>(&hi);
    return u;
}

// ---------------------------------------------------------------------------
// Kernel 1: per-group normalize + KL + diag + Z init (unchanged — passed R1)
// ---------------------------------------------------------------------------
__global__ void __launch_bounds__(256) prep_kernel(const float* __restrict__ emb,
                                                   const float* __restrict__ scores) {
    const int b    = blockIdx.x;
    const int tid  = threadIdx.x;
    const int lane = tid & 31;
    const int warp = tid >> 5;

    __shared__ float s_part[10][8];
    __shared__ float s_inv[10];
    __shared__ float s_cos[9];

    float4 v[RSZ];
    const float4* e4 = reinterpret_cast<const float4*>(emb) + (size_t)b * RSZ * (DIM / 4);
#pragma unroll
    for (int r = 0; r < RSZ; ++r) v[r] = e4[(size_t)r * (DIM / 4) + tid];

#pragma unroll
    for (int r = 0; r < RSZ; ++r) {
        float p = v[r].x * v[r].x + v[r].y * v[r].y + v[r].z * v[r].z + v[r].w * v[r].w;
        p = warpReduceSum(p);
        if (lane == 0) s_part[r][warp] = p;
    }
    __syncthreads();
    if (tid < RSZ) {
        float ss = 0.f;
#pragma unroll
        for (int w = 0; w < 8; ++w) ss += s_part[tid][w];
        s_inv[tid] = 1.0f / fmaxf(sqrtf(ss), 1e-12f);
    }
    __syncthreads();

    const float inv0 = s_inv[0];
    {
        float4 a = v[0];
        a.x *= inv0; a.y *= inv0; a.z *= inv0; a.w *= inv0;
        reinterpret_cast<uint2*>(g_an + (size_t)b * DIM)[tid] = pack_bf16x4(a);
    }
#pragma unroll
    for (int r = 1; r < RSZ; ++r) {
        const float invr = s_inv[r];
        float4 t = v[r];
        t.x *= invr; t.y *= invr; t.z *= invr; t.w *= invr;
        size_t drow = (r == 1) ? (size_t)b
                               : (size_t)B_ROWS + (size_t)b * (RSZ - 2) + (size_t)(r - 2);
        reinterpret_cast<uint2*>(g_tn + drow * DIM)[tid] = pack_bf16x4(t);
    }

#pragma unroll
    for (int r = 1; r < RSZ; ++r) {
        float d = v[0].x * v[r].x + v[0].y * v[r].y + v[0].z * v[r].z + v[0].w * v[r].w;
        d = warpReduceSum(d);
        if (lane == 0) s_part[r - 1][warp] = d;
    }
    __syncthreads();
    if (tid < RSZ - 1) {
        float d = 0.f;
#pragma unroll
        for (int w = 0; w < 8; ++w) d += s_part[tid][w];
        s_cos[tid] = d * s_inv[0] * s_inv[tid + 1];
    }
    __syncthreads();

    if (tid == 0) {
        float rs[9], sc[9];
#pragma unroll
        for (int k = 0; k < 9; ++k) { rs[k] = s_cos[k]; sc[k] = scores[(size_t)b * 9 + k]; }
        float m1 = sc[0], m2 = rs[0];
#pragma unroll
        for (int k = 1; k < 9; ++k) { m1 = fmaxf(m1, sc[k]); m2 = fmaxf(m2, rs[k]); }
        float z1 = 0.f, z2 = 0.f;
#pragma unroll
        for (int k = 0; k < 9; ++k) { z1 += expf(sc[k] - m1); z2 += expf(rs[k] - m2); }
        const float lz1 = logf(z1), lz2 = logf(z2);
        float kl = 0.f;
#pragma unroll
        for (int k = 0; k < 9; ++k) {
            float lce = sc[k] - m1 - lz1;
            float ce  = expf(lce);
            float lp  = rs[k] - m2 - lz2;
            kl += ce * (lce - lp);
        }
        g_kl[b]   = kl / (float)(RSZ - 1);
        g_diag[b] = rs[0] * INV_TEMP;
        g_Z[b]    = 0.0f;
    }
}

// ---------------------------------------------------------------------------
// Kernel 2: HMMA GEMM (a_n @ t_n^T) + exp row-sum.
// CTA tile 128x256, warp tile 64x64 (2x4 warps), K=32/stage, 4-stage cp.async.
// ---------------------------------------------------------------------------
#define TILE_M  128
#define TILE_N  256
#define STAGES  4
#define NUM_KT  32                       // 1024 / 32
#define A_STG   (TILE_M * 80)            // 10240 B (80B stride rows, 64B data)
#define B_STG   (TILE_N * 80)            // 20480 B
#define STG_B   (A_STG + B_STG)          // 30720 B per stage
#define GEMM_SMEM_TOTAL (STAGES * STG_B) // 122880 B

__device__ __forceinline__ void ldsm_x4(uint32_t addr, uint32_t* r) {
    asm volatile("ldmatrix.sync.aligned.m8n8.x4.shared.b16 {%0,%1,%2,%3}, [%4];"
                 : "=r"(r[0]), "=r"(r[1]), "=r"(r[2]), "=r"(r[3])
                 : "r"(addr));
}
__device__ __forceinline__ void mma_bf16(float* d, const uint32_t* a, uint32_t b0, uint32_t b1) {
    asm volatile(
        "mma.sync.aligned.m16n8k16.row.col.f32.bf16.bf16.f32 "
        "{%0,%1,%2,%3}, {%4,%5,%6,%7}, {%8,%9}, {%0,%1,%2,%3};"
        : "+f"(d[0]), "+f"(d[1]), "+f"(d[2]), "+f"(d[3])
        : "r"(a[0]), "r"(a[1]), "r"(a[2]), "r"(a[3]), "r"(b0), "r"(b1));
}
__device__ __forceinline__ void cp_async_16(uint32_t dst, const void* src) {
    asm volatile("cp.async.cg.shared.global [%0], [%1], 16;" :: "r"(dst), "l"(src));
}

__global__ void __launch_bounds__(256, 1) gemm_z_kernel() {
    extern __shared__ char smem[];
    const uint32_t sb = (uint32_t)__cvta_generic_to_shared(smem);

    const int bn   = blockIdx.x;     // 0..71  (256 targets each)
    const int bm   = blockIdx.y;     // 0..15  (128 anchors each)
    const int tid  = threadIdx.x;
    const int lane = tid & 31;
    const int warp = tid >> 5;
    const int wm   = warp & 1;       // 2 warps along M (64 rows)
    const int wn   = warp >> 1;      // 4 warps along N (64 cols)

    float acc[4][8][4];
#pragma unroll
    for (int i = 0; i < 4; ++i)
#pragma unroll
        for (int j = 0; j < 8; ++j)
#pragma unroll
            for (int c = 0; c < 4; ++c) acc[i][j][c] = 0.f;

    // ---- load geometry: thread -> (row = tid>>2, chunk c = tid&3) ----
    const int lrow = tid >> 2;       // 0..63
    const int c    = tid & 3;        // 16B chunk within 64B K-slice
    const char* gA = (const char*)g_an + ((size_t)(bm * TILE_M + lrow)) * 2048 + c * 16;
    const char* gB = (const char*)g_tn + ((size_t)(bn * TILE_N + lrow)) * 2048 + c * 16;
    const uint32_t sA0 = sb + lrow * 80 + c * 16;
    const uint32_t sB0 = sb + A_STG + lrow * 80 + c * 16;

    auto issue_loads = [&](int slot, int kt) {
        const size_t ko = (size_t)kt * 64;
        const uint32_t so = slot * STG_B;
#pragma unroll
        for (int p = 0; p < 2; ++p)
            cp_async_16(sA0 + so + p * (64 * 80), gA + ko + (size_t)p * (64 * 2048));
#pragma unroll
        for (int p = 0; p < 4; ++p)
            cp_async_16(sB0 + so + p * (64 * 80), gB + ko + (size_t)p * (64 * 2048));
        asm volatile("cp.async.commit_group;");
    };

    // prologue: 3 stages in flight
#pragma unroll
    for (int s = 0; s < STAGES - 1; ++s) issue_loads(s, s);

    // fragment addressing
    const uint32_t aRowBase = (uint32_t)(wm * 64 + (lane & 15));
    const uint32_t bRowBase = (uint32_t)(wn * 64 + (lane & 15));
    const uint32_t halfoff  = ((uint32_t)(lane >> 4)) << 4;

    for (int it = 0; it < NUM_KT; ++it) {
        const int slot = it & (STAGES - 1);

        if (it < NUM_KT - 2)       asm volatile("cp.async.wait_group 2;" ::: "memory");
        else if (it == NUM_KT - 2) asm volatile("cp.async.wait_group 1;" ::: "memory");
        else                       asm volatile("cp.async.wait_group 0;" ::: "memory");
        __syncthreads();

        if (it + STAGES - 1 < NUM_KT)
            issue_loads((it + STAGES - 1) & (STAGES - 1), it + STAGES - 1);

        const uint32_t saStage = sb + slot * STG_B;
        const uint32_t sbStage = saStage + A_STG;

#pragma unroll
        for (int kk = 0; kk < 2; ++kk) {
            const uint32_t byteoff = halfoff + kk * 32;
            uint32_t af[4][4], bf[4][4];
#pragma unroll
            for (int mi = 0; mi < 4; ++mi)
                ldsm_x4(saStage + (aRowBase + mi * 16) * 80u + byteoff, af[mi]);
#pragma unroll
            for (int nt = 0; nt < 4; ++nt)
                ldsm_x4(sbStage + (bRowBase + nt * 16) * 80u + byteoff, bf[nt]);
#pragma unroll
            for (int mi = 0; mi < 4; ++mi)
#pragma unroll
                for (int nt = 0; nt < 4; ++nt) {
                    mma_bf16(acc[mi][nt * 2 + 0], af[mi], bf[nt][0], bf[nt][2]);
                    mma_bf16(acc[mi][nt * 2 + 1], af[mi], bf[nt][1], bf[nt][3]);
                }
        }
    }
    __syncthreads();   // all warps done with smem stages; reuse smem for reduction

    // ---- epilogue: exp + row-sum. smem reduce across the 4 N-warps ----
    float* sZ = (float*)smem;
    if (tid < TILE_M) sZ[tid] = 0.f;
    __syncthreads();

#pragma unroll
    for (int mi = 0; mi < 4; ++mi) {
        float s0 = 0.f, s1 = 0.f;
#pragma unroll
        for (int ni = 0; ni < 8; ++ni) {
            s0 += __expf(acc[mi][ni][0] * INV_TEMP) + __expf(acc[mi][ni][1] * INV_TEMP);
            s1 += __expf(acc[mi][ni][2] * INV_TEMP) + __expf(acc[mi][ni][3] * INV_TEMP);
        }
        s0 += __shfl_xor_sync(0xffffffffu, s0, 1);
        s0 += __shfl_xor_sync(0xffffffffu, s0, 2);
        s1 += __shfl_xor_sync(0xffffffffu, s1, 1);
        s1 += __shfl_xor_sync(0xffffffffu, s1, 2);
        if ((lane & 3) == 0) {
            const int rl = wm * 64 + mi * 16 + (lane >> 2);
            atomicAdd(&sZ[rl],     s0);
            atomicAdd(&sZ[rl + 8], s1);
        }
    }
    __syncthreads();
    if (tid < TILE_M) atomicAdd(&g_Z[bm * TILE_M + tid], sZ[tid]);
}

// ---------------------------------------------------------------------------
// Kernel 3: final scalar reduction
// ---------------------------------------------------------------------------
__global__ void __launch_bounds__(256) finalize_kernel(float* __restrict__ out) {
    const int tid  = threadIdx.x;
    const int lane = tid & 31;
    const int warp = tid >> 5;
    __shared__ float skl[8], sce[8];

    float akl = 0.f, ace = 0.f;
    for (int b = tid; b < B_ROWS; b += 256) {
        akl += g_kl[b];
        ace += logf(g_Z[b]) - g_diag[b];
    }
    akl = warpReduceSum(akl);
    ace = warpReduceSum(ace);
    if (lane == 0) { skl[warp] = akl; sce[warp] = ace; }
    __syncthreads();
    if (tid == 0) {
        float k = 0.f, c2 = 0.f;
#pragma unroll
        for (int w = 0; w < 8; ++w) { k += skl[w]; c2 += sce[w]; }
        out[0] = BETA_C * (k / (float)B_ROWS) + ALPHA_C * (c2 / (float)B_ROWS);
    }
}

// ---------------------------------------------------------------------------
extern "C" void kernel_launch(void* const* d_in, const int* in_sizes, int n_in,
                              void* d_out, int out_size) {
    const float* emb    = (const float*)d_in[0];
    const float* scores = (const float*)d_in[1];

    cudaFuncSetAttribute(gemm_z_kernel,
                         cudaFuncAttributeMaxDynamicSharedMemorySize, GEMM_SMEM_TOTAL);

    prep_kernel<<<B_ROWS, 256>>>(emb, scores);
    dim3 grid(NTGT / TILE_N, B_ROWS / TILE_M);   // (72, 16)
    gemm_z_kernel<<<grid, 256, GEMM_SMEM_TOTAL>>>();
    finalize_kernel<<<1, 256>>>((float*)d_out);
}

// round 4
// speedup vs baseline: 1.6869x; 1.6869x over previous
#include <cuda_runtime.h>
#include <cuda_bf16.h>
#include <stdint.h>

// Problem constants (fixed shapes)
#define B_ROWS 2048
#define RSZ    10
#define DIM    1024
#define NTGT   (B_ROWS * (RSZ - 1))   // 18432 targets
#define INV_TEMP 20.0f
#define ALPHA_C  1.0f
#define BETA_C   0.5f

// ---------------- device scratch ----------------
__device__ uint32_t g_qa[(size_t)B_ROWS * (DIM / 4)];  // int8 anchors (packed x4)
__device__ uint32_t g_qt[(size_t)NTGT * (DIM / 4)];    // int8 targets (packed x4)
__device__ float g_sa[B_ROWS];   // anchor dequant scale (maxabs/127)
__device__ float g_st[NTGT];     // target dequant scale
__device__ float g_diag[B_ROWS];
__device__ float g_kl[B_ROWS];
__device__ float g_Z[B_ROWS];

__device__ __forceinline__ float warpReduceSum(float v) {
    v += __shfl_xor_sync(0xffffffffu, v, 16);
    v += __shfl_xor_sync(0xffffffffu, v, 8);
    v += __shfl_xor_sync(0xffffffffu, v, 4);
    v += __shfl_xor_sync(0xffffffffu, v, 2);
    v += __shfl_xor_sync(0xffffffffu, v, 1);
    return v;
}
__device__ __forceinline__ float warpReduceMax(float v) {
    v = fmaxf(v, __shfl_xor_sync(0xffffffffu, v, 16));
    v = fmaxf(v, __shfl_xor_sync(0xffffffffu, v, 8));
    v = fmaxf(v, __shfl_xor_sync(0xffffffffu, v, 4));
    v = fmaxf(v, __shfl_xor_sync(0xffffffffu, v, 2));
    v = fmaxf(v, __shfl_xor_sync(0xffffffffu, v, 1));
    return v;
}

// ---------------------------------------------------------------------------
// Kernel 1: per-group normalize + int8 quantize + KL + diag + Z init.
// ---------------------------------------------------------------------------
__global__ void __launch_bounds__(256) prep_kernel(const float* __restrict__ emb,
                                                   const float* __restrict__ scores) {
    const int b    = blockIdx.x;
    const int tid  = threadIdx.x;
    const int lane = tid & 31;
    const int warp = tid >> 5;

    __shared__ float s_part[10][8];
    __shared__ float s_maxp[10][8];
    __shared__ float s_qs[10];       // inv_norm * 127/maxabs_norm (quant multiplier)
    __shared__ float s_inv[10];
    __shared__ float s_cos[9];

    float4 v[RSZ];
    const float4* e4 = reinterpret_cast<const float4*>(emb) + (size_t)b * RSZ * (DIM / 4);
#pragma unroll
    for (int r = 0; r < RSZ; ++r) v[r] = e4[(size_t)r * (DIM / 4) + tid];

#pragma unroll
    for (int r = 0; r < RSZ; ++r) {
        float p = v[r].x * v[r].x + v[r].y * v[r].y + v[r].z * v[r].z + v[r].w * v[r].w;
        float m = fmaxf(fmaxf(fabsf(v[r].x), fabsf(v[r].y)),
                        fmaxf(fabsf(v[r].z), fabsf(v[r].w)));
        p = warpReduceSum(p);
        m = warpReduceMax(m);
        if (lane == 0) { s_part[r][warp] = p; s_maxp[r][warp] = m; }
    }
    __syncthreads();
    if (tid < RSZ) {
        float ss = 0.f, mm = 0.f;
#pragma unroll
        for (int w = 0; w < 8; ++w) { ss += s_part[tid][w]; mm = fmaxf(mm, s_maxp[tid][w]); }
        const float inv = 1.0f / fmaxf(sqrtf(ss), 1e-12f);
        const float mn  = fmaxf(mm * inv, 1e-20f);   // maxabs of normalized row
        s_inv[tid] = inv;
        s_qs[tid]  = inv * (127.0f / mn);
        const float dq = mn * (1.0f / 127.0f);
        if      (tid == 0) g_sa[b] = dq;
        else if (tid == 1) g_st[b] = dq;
        else               g_st[B_ROWS + (size_t)b * 8 + (tid - 2)] = dq;
    }
    __syncthreads();

    // quantize + pack 4 int8 per thread per row
#pragma unroll
    for (int r = 0; r < RSZ; ++r) {
        const float qs = s_qs[r];
        int x0 = min(127, max(-127, __float2int_rn(v[r].x * qs)));
        int x1 = min(127, max(-127, __float2int_rn(v[r].y * qs)));
        int x2 = min(127, max(-127, __float2int_rn(v[r].z * qs)));
        int x3 = min(127, max(-127, __float2int_rn(v[r].w * qs)));
        uint32_t pk = (uint32_t)(x0 & 255) | ((uint32_t)(x1 & 255) << 8) |
                      ((uint32_t)(x2 & 255) << 16) | ((uint32_t)x3 << 24);
        if (r == 0) {
            g_qa[(size_t)b * 256 + tid] = pk;
        } else {
            size_t drow = (r == 1) ? (size_t)b
                                   : (size_t)B_ROWS + (size_t)b * 8 + (size_t)(r - 2);
            g_qt[drow * 256 + tid] = pk;
        }
    }

    // fp32 cosines anchor . row_r (KL + diag)
#pragma unroll
    for (int r = 1; r < RSZ; ++r) {
        float d = v[0].x * v[r].x + v[0].y * v[r].y + v[0].z * v[r].z + v[0].w * v[r].w;
        d = warpReduceSum(d);
        if (lane == 0) s_part[r - 1][warp] = d;
    }
    __syncthreads();
    if (tid < RSZ - 1) {
        float d = 0.f;
#pragma unroll
        for (int w = 0; w < 8; ++w) d += s_part[tid][w];
        s_cos[tid] = d * s_inv[0] * s_inv[tid + 1];
    }
    __syncthreads();

    if (tid == 0) {
        float rs[9], sc[9];
#pragma unroll
        for (int k = 0; k < 9; ++k) { rs[k] = s_cos[k]; sc[k] = scores[(size_t)b * 9 + k]; }
        float m1 = sc[0], m2 = rs[0];
#pragma unroll
        for (int k = 1; k < 9; ++k) { m1 = fmaxf(m1, sc[k]); m2 = fmaxf(m2, rs[k]); }
        float z1 = 0.f, z2 = 0.f;
#pragma unroll
        for (int k = 0; k < 9; ++k) { z1 += expf(sc[k] - m1); z2 += expf(rs[k] - m2); }
        const float lz1 = logf(z1), lz2 = logf(z2);
        float kl = 0.f;
#pragma unroll
        for (int k = 0; k < 9; ++k) {
            float lce = sc[k] - m1 - lz1;
            float ce  = expf(lce);
            float lp  = rs[k] - m2 - lz2;
            kl += ce * (lce - lp);
        }
        g_kl[b]   = kl / (float)(RSZ - 1);
        g_diag[b] = rs[0] * INV_TEMP;
        g_Z[b]    = 0.0f;
    }
}

// ---------------------------------------------------------------------------
// Kernel 2: int8 IMMA GEMM (qa @ qt^T) + dequant + exp row-sum.
// CTA tile 128x256, warp tile 64x64 (2x4), K=64/stage, 4-stage cp.async.
// mma.sync.m16n8k32.s8 — 4096 MACs/instr (2x the bf16 HMMA).
// ---------------------------------------------------------------------------
#define TILE_M  128
#define TILE_N  256
#define STAGES  4
#define NUM_KT  16                       // 1024 / 64
#define A_STG   (TILE_M * 80)            // 10240 B (80B stride rows, 64B payload)
#define B_STG   (TILE_N * 80)            // 20480 B
#define STG_B   (A_STG + B_STG)          // 30720 B per stage
#define GEMM_SMEM_TOTAL (STAGES * STG_B) // 122880 B

__device__ __forceinline__ void ldsm_x4(uint32_t addr, uint32_t* r) {
    asm volatile("ldmatrix.sync.aligned.m8n8.x4.shared.b16 {%0,%1,%2,%3}, [%4];"
                 : "=r"(r[0]), "=r"(r[1]), "=r"(r[2]), "=r"(r[3])
                 : "r"(addr));
}
__device__ __forceinline__ void mma_s8(int* d, const uint32_t* a, uint32_t b0, uint32_t b1) {
    asm volatile(
        "mma.sync.aligned.m16n8k32.row.col.s32.s8.s8.s32 "
        "{%0,%1,%2,%3}, {%4,%5,%6,%7}, {%8,%9}, {%0,%1,%2,%3};"
        : "+r"(d[0]), "+r"(d[1]), "+r"(d[2]), "+r"(d[3])
        : "r"(a[0]), "r"(a[1]), "r"(a[2]), "r"(a[3]), "r"(b0), "r"(b1));
}
__device__ __forceinline__ void cp_async_16(uint32_t dst, const void* src) {
    asm volatile("cp.async.cg.shared.global [%0], [%1], 16;" :: "r"(dst), "l"(src));
}

__global__ void __launch_bounds__(256, 1) gemm_z_kernel() {
    extern __shared__ char smem[];
    const uint32_t sb = (uint32_t)__cvta_generic_to_shared(smem);

    const int bn   = blockIdx.x;     // 0..71  (256 targets)
    const int bm   = blockIdx.y;     // 0..15  (128 anchors)
    const int tid  = threadIdx.x;
    const int lane = tid & 31;
    const int warp = tid >> 5;
    const int wm   = warp & 1;       // 2 warps along M
    const int wn   = warp >> 1;      // 4 warps along N

    int acc[4][8][4];
#pragma unroll
    for (int i = 0; i < 4; ++i)
#pragma unroll
        for (int j = 0; j < 8; ++j)
#pragma unroll
            for (int c = 0; c < 4; ++c) acc[i][j][c] = 0;

    // ---- load geometry: row = tid>>2 (64 rows/pass), chunk = tid&3 (16B of 64B) ----
    const int lrow = tid >> 2;
    const int c    = tid & 3;
    const char* gA = (const char*)g_qa + ((size_t)(bm * TILE_M + lrow)) * 1024 + c * 16;
    const char* gB = (const char*)g_qt + ((size_t)(bn * TILE_N + lrow)) * 1024 + c * 16;
    const uint32_t sA0 = sb + lrow * 80 + c * 16;
    const uint32_t sB0 = sb + A_STG + lrow * 80 + c * 16;

    auto issue_loads = [&](int slot, int kt) {
        const size_t ko = (size_t)kt * 64;         // 64 bytes = K 64 int8
        const uint32_t so = slot * STG_B;
#pragma unroll
        for (int p = 0; p < 2; ++p)
            cp_async_16(sA0 + so + p * (64 * 80), gA + ko + (size_t)p * (64 * 1024));
#pragma unroll
        for (int p = 0; p < 4; ++p)
            cp_async_16(sB0 + so + p * (64 * 80), gB + ko + (size_t)p * (64 * 1024));
        asm volatile("cp.async.commit_group;");
    };

#pragma unroll
    for (int s = 0; s < STAGES - 1; ++s) issue_loads(s, s);

    const uint32_t aRowBase = (uint32_t)(wm * 64 + (lane & 15));
    const uint32_t bRowBase = (uint32_t)(wn * 64 + (lane & 15));
    const uint32_t halfoff  = ((uint32_t)(lane >> 4)) << 4;

    for (int it = 0; it < NUM_KT; ++it) {
        const int slot = it & (STAGES - 1);

        if (it < NUM_KT - 2)       asm volatile("cp.async.wait_group 2;" ::: "memory");
        else if (it == NUM_KT - 2) asm volatile("cp.async.wait_group 1;" ::: "memory");
        else                       asm volatile("cp.async.wait_group 0;" ::: "memory");
        __syncthreads();

        if (it + STAGES - 1 < NUM_KT)
            issue_loads((it + STAGES - 1) & (STAGES - 1), it + STAGES - 1);

        const uint32_t saStage = sb + slot * STG_B;
        const uint32_t sbStage = saStage + A_STG;

#pragma unroll
        for (int kk = 0; kk < 2; ++kk) {           // each kk = K 32 int8 (32 B/row)
            const uint32_t byteoff = halfoff + kk * 32;
            uint32_t af[4][4], bf[4][4];
#pragma unroll
            for (int mi = 0; mi < 4; ++mi)
                ldsm_x4(saStage + (aRowBase + mi * 16) * 80u + byteoff, af[mi]);
#pragma unroll
            for (int nt = 0; nt < 4; ++nt)
                ldsm_x4(sbStage + (bRowBase + nt * 16) * 80u + byteoff, bf[nt]);
#pragma unroll
            for (int mi = 0; mi < 4; ++mi)
#pragma unroll
                for (int nt = 0; nt < 4; ++nt) {
                    mma_s8(acc[mi][nt * 2 + 0], af[mi], bf[nt][0], bf[nt][2]);
                    mma_s8(acc[mi][nt * 2 + 1], af[mi], bf[nt][1], bf[nt][3]);
                }
        }
    }
    __syncthreads();   // stages dead; reuse smem

    // ---- epilogue: stage scales, dequant, exp, row-reduce ----
    float* sSa = (float*)smem;               // [0,128)
    float* sSt = (float*)smem + 128;         // [128,384)
    float* sZ  = (float*)smem + 384;         // [384,512)
    if (tid < 128) { sSa[tid] = g_sa[bm * TILE_M + tid]; sZ[tid] = 0.f; }
    if (tid < 256)   sSt[tid] = g_st[bn * TILE_N + tid];
    __syncthreads();

#pragma unroll
    for (int mi = 0; mi < 4; ++mi) {
        const int row0 = wm * 64 + mi * 16 + (lane >> 2);
        const float a0 = sSa[row0]     * INV_TEMP;
        const float a1 = sSa[row0 + 8] * INV_TEMP;
        float s0 = 0.f, s1 = 0.f;
#pragma unroll
        for (int ni = 0; ni < 8; ++ni) {
            const int col = wn * 64 + ni * 8 + 2 * (lane & 3);
            const float b0 = sSt[col], b1 = sSt[col + 1];
            s0 += __expf((float)acc[mi][ni][0] * a0 * b0)
                + __expf((float)acc[mi][ni][1] * a0 * b1);
            s1 += __expf((float)acc[mi][ni][2] * a1 * b0)
                + __expf((float)acc[mi][ni][3] * a1 * b1);
        }
        s0 += __shfl_xor_sync(0xffffffffu, s0, 1);
        s0 += __shfl_xor_sync(0xffffffffu, s0, 2);
        s1 += __shfl_xor_sync(0xffffffffu, s1, 1);
        s1 += __shfl_xor_sync(0xffffffffu, s1, 2);
        if ((lane & 3) == 0) {
            const int rl = wm * 64 + mi * 16 + (lane >> 2);
            atomicAdd(&sZ[rl],     s0);
            atomicAdd(&sZ[rl + 8], s1);
        }
    }
    __syncthreads();
    if (tid < TILE_M) atomicAdd(&g_Z[bm * TILE_M + tid], sZ[tid]);
}

// ---------------------------------------------------------------------------
// Kernel 3: final scalar reduction
// ---------------------------------------------------------------------------
__global__ void __launch_bounds__(256) finalize_kernel(float* __restrict__ out) {
    const int tid  = threadIdx.x;
    const int lane = tid & 31;
    const int warp = tid >> 5;
    __shared__ float skl[8], sce[8];

    float akl = 0.f, ace = 0.f;
    for (int b = tid; b < B_ROWS; b += 256) {
        akl += g_kl[b];
        ace += logf(g_Z[b]) - g_diag[b];
    }
    akl = warpReduceSum(akl);
    ace = warpReduceSum(ace);
    if (lane == 0) { skl[warp] = akl; sce[warp] = ace; }
    __syncthreads();
    if (tid == 0) {
        float k = 0.f, c2 = 0.f;
#pragma unroll
        for (int w = 0; w < 8; ++w) { k += skl[w]; c2 += sce[w]; }
        out[0] = BETA_C * (k / (float)B_ROWS) + ALPHA_C * (c2 / (float)B_ROWS);
    }
}

// ---------------------------------------------------------------------------
extern "C" void kernel_launch(void* const* d_in, const int* in_sizes, int n_in,
                              void* d_out, int out_size) {
    const float* emb    = (const float*)d_in[0];
    const float* scores = (const float*)d_in[1];

    cudaFuncSetAttribute(gemm_z_kernel,
                         cudaFuncAttributeMaxDynamicSharedMemorySize, GEMM_SMEM_TOTAL);

    prep_kernel<<<B_ROWS, 256>>>(emb, scores);
    dim3 grid(NTGT / TILE_N, B_ROWS / TILE_M);   // (72, 16)
    gemm_z_kernel<<<grid, 256, GEMM_SMEM_TOTAL>>>();
    finalize_kernel<<<1, 256>>>((float*)d_out);
}